// round 8
// baseline (speedup 1.0000x reference)
#include <cuda_runtime.h>
#include <math.h>

#define K_BINS   8
#define TAIL     3.0f
#define MIN_W    0.001f
#define MIN_H    0.001f
#define MIN_D    0.001f

#define NROWS    8192
#define NDIMS    2048
#define NPAR     (K_BINS * 3 - 1)   // 23

#define TILE_D   64                  // columns per block
#define THREADS  128                 // 32 col-pairs x 4 row slots
#define ROWS_PB  64                  // rows per block (4 slots x 16 rows)

__global__ __launch_bounds__(THREADS, 8)
void rqs_kernel(const float* __restrict__ inputs,
                const float* __restrict__ params,
                float* __restrict__ out_base)
{
    // tables interleaved by column parity so paired-column threads stay conflict-free:
    //   sm_f4[bin][par][t] = {invw, c, ih, ich}   for col = 2t+par
    //   sm_f2[bin][par][t] = {dlo, s}
    // element lookup lane addr: idx*1024 + par*512 + 16*t  (16B stride -> conflict-free)
    __shared__ float4 sm_f4[K_BINS][2][TILE_D / 2];   // 8 KB
    __shared__ float2 sm_f2[K_BINS][2][TILE_D / 2];   // 4 KB
    __shared__ float  sm_kn[7][TILE_D];               // 1.75 KB

    const int tid  = threadIdx.x;
    const int col0 = blockIdx.x * TILE_D;

    // ---------------- table build: one thread per dim ----------------
    if (tid < TILE_D) {
        const float* p = params + (size_t)(col0 + tid) * NPAR;
        float uw[K_BINS], uh[K_BINS], ud[K_BINS - 1];
        #pragma unroll
        for (int j = 0; j < K_BINS; j++)      uw[j] = p[j];
        #pragma unroll
        for (int j = 0; j < K_BINS; j++)      uh[j] = p[K_BINS + j];
        #pragma unroll
        for (int j = 0; j < K_BINS - 1; j++)  ud[j] = p[2 * K_BINS + j];

        float cw[K_BINS + 1], ch[K_BINS + 1];
        {
            float m = uw[0];
            #pragma unroll
            for (int j = 1; j < K_BINS; j++) m = fmaxf(m, uw[j]);
            float e[K_BINS], ssum = 0.0f;
            #pragma unroll
            for (int j = 0; j < K_BINS; j++) { e[j] = expf(uw[j] - m); ssum += e[j]; }
            float inv_s = 1.0f / ssum;
            float acc = 0.0f;
            cw[0] = -TAIL;
            #pragma unroll
            for (int j = 0; j < K_BINS; j++) {
                float wj = fmaf(1.0f - MIN_W * K_BINS, e[j] * inv_s, MIN_W);
                acc += wj;
                cw[j + 1] = fmaf(2.0f * TAIL, acc, -TAIL);
            }
            cw[K_BINS] = TAIL;
        }
        {
            float m = uh[0];
            #pragma unroll
            for (int j = 1; j < K_BINS; j++) m = fmaxf(m, uh[j]);
            float e[K_BINS], ssum = 0.0f;
            #pragma unroll
            for (int j = 0; j < K_BINS; j++) { e[j] = expf(uh[j] - m); ssum += e[j]; }
            float inv_s = 1.0f / ssum;
            float acc = 0.0f;
            ch[0] = -TAIL;
            #pragma unroll
            for (int j = 0; j < K_BINS; j++) {
                float hj = fmaf(1.0f - MIN_H * K_BINS, e[j] * inv_s, MIN_H);
                acc += hj;
                ch[j + 1] = fmaf(2.0f * TAIL, acc, -TAIL);
            }
            ch[K_BINS] = TAIL;
        }
        float dv[K_BINS + 1];
        dv[0] = 1.0f;                  // MIN_D + softplus(log(exp(1-MIN_D)-1)) == 1
        dv[K_BINS] = 1.0f;
        #pragma unroll
        for (int j = 0; j < K_BINS - 1; j++)
            dv[j + 1] = MIN_D + log1pf(expf(ud[j]));

        #pragma unroll
        for (int j = 0; j < 7; j++) sm_kn[j][tid] = cw[j + 1];

        const int par = tid & 1;
        const int t   = tid >> 1;
        #pragma unroll
        for (int b = 0; b < K_BINS; b++) {
            const float iw    = cw[b + 1] - cw[b];
            const float ih    = ch[b + 1] - ch[b];
            const float invw  = 1.0f / iw;
            const float delta = ih * invw;
            const float dlo   = dv[b];
            const float s     = dlo + dv[b + 1] - 2.0f * delta;
            sm_f4[b][par][t] = make_float4(invw, -cw[b] * invw, ih, ch[b]);
            sm_f2[b][par][t] = make_float2(dlo, s);
        }
    }
    __syncthreads();

    // ---------------- main loop: 2 columns per thread ----------------
    const int tx  = tid & 31;                    // col-pair index
    const int ty  = tid >> 5;                    // row slot 0..3
    const int col = col0 + 2 * tx;
    const int row0 = blockIdx.y * ROWS_PB + ty;

    // knots for both columns -> registers
    float ka[7], kb[7];
    #pragma unroll
    for (int j = 0; j < 7; j++) { ka[j] = sm_kn[j][2 * tx]; kb[j] = sm_kn[j][2 * tx + 1]; }

    const float4* __restrict__ fA0 = &sm_f4[0][0][tx];   // + idx*(TILE_D) float4? stride = 2*(TILE_D/2)=64 float4 per bin
    const float4* __restrict__ fA1 = &sm_f4[0][1][tx];
    const float2* __restrict__ fB0 = &sm_f2[0][0][tx];
    const float2* __restrict__ fB1 = &sm_f2[0][1][tx];
    const int FS4 = 2 * (TILE_D / 2);   // float4 elements between bins (64)
    const int FS2 = 2 * (TILE_D / 2);   // float2 elements between bins (64)

    const size_t base = (size_t)row0 * NDIMS + col;
    const float2* __restrict__ pin = (const float2*)(inputs + base);
    float2* __restrict__ po = (float2*)(out_base + base);
    float2* __restrict__ pl = (float2*)(out_base + (size_t)NROWS * NDIMS + base);
    const int RSTRIDE = 4 * NDIMS / 2;           // float2 units per 4-row step

    #pragma unroll 1
    for (int ii = 0; ii < 4; ii++) {
        float2 gv[4];
        #pragma unroll
        for (int j = 0; j < 4; j++) gv[j] = pin[j * RSTRIDE];

        #pragma unroll
        for (int j = 0; j < 4; j++) {
            float res_o[2], res_l[2];
            #pragma unroll
            for (int c = 0; c < 2; c++) {
                const float g = c ? gv[j].y : gv[j].x;
                const float* kk = c ? kb : ka;

                const bool p3 = g >= kk[3];
                const float m1 = p3 ? kk[5] : kk[1];
                const bool p2 = g >= m1;
                const float hi = p2 ? kk[6] : kk[4];
                const float lo = p2 ? kk[2] : kk[0];
                const float m2 = p3 ? hi : lo;
                const bool p1 = g >= m2;
                const int idx = (p3 ? 4 : 0) + (p2 ? 2 : 0) + (p1 ? 1 : 0);

                const float4 A = c ? fA1[idx * FS4] : fA0[idx * FS4];
                const float2 B = c ? fB1[idx * FS2] : fB0[idx * FS2];

                const float delta = A.z * A.x;           // ih * invw
                const float th  = fmaf(g, A.x, A.y);     // theta
                const float th2 = th * th;
                const float t1m = th - th2;

                const float den  = fmaf(B.y, t1m, delta);
                const float rden = __fdividef(1.0f, den);

                const float nm = fmaf(delta, th2, B.x * t1m);
                const float o  = fmaf(A.z * nm, rden, A.w);

                const float dmd = delta - B.x;
                const float dn  = fmaf(fmaf(B.y, th, dmd + dmd), th, B.x);
                const float dd  = delta * rden;
                const float l   = __logf(dn * (dd * dd));

                const bool inside = fabsf(g) <= TAIL;
                res_o[c] = inside ? o : g;
                res_l[c] = inside ? l : 0.0f;
            }
            po[j * RSTRIDE] = make_float2(res_o[0], res_o[1]);
            pl[j * RSTRIDE] = make_float2(res_l[0], res_l[1]);
        }
        pin += 4 * RSTRIDE;
        po  += 4 * RSTRIDE;
        pl  += 4 * RSTRIDE;
    }
}

extern "C" void kernel_launch(void* const* d_in, const int* in_sizes, int n_in,
                              void* d_out, int out_size)
{
    const float* inputs = (const float*)d_in[0];
    const float* params = (const float*)d_in[1];
    float* out = (float*)d_out;

    dim3 grid(NDIMS / TILE_D, NROWS / ROWS_PB);   // (32, 128)
    rqs_kernel<<<grid, THREADS>>>(inputs, params, out);
}